// round 16
// baseline (speedup 1.0000x reference)
#include <cuda_runtime.h>
#include <math.h>

#define BGRAPHS 32768
#define NPG 54
#define EPG 144
#define ETOT (BGRAPHS * EPG)
#define ACTP 228            // padded act row (226 used)
#define SLOT 18             // slots per node
#define XP 12               // x row pad (floats)  -> 48 B rows, 16-aligned
#define HP 20               // h1 row pad (floats) -> 80 B rows, 16-aligned

// Staging: concat([embeds, g]) rows [B, 228]; partial out sums [2][B]
__device__ __align__(16) float g_act[(size_t)BGRAPHS * ACTP];
__device__ __align__(16) float g_partial[2 * BGRAPHS];

// ---------------- constant weights (graph-captured D2D copies) -------------
__constant__ __align__(16) float c_w1rel[8 * 16];
__constant__ __align__(16) float c_w1root[8 * 16];
__constant__ __align__(16) float c_b1[16];
__constant__ __align__(16) float c_w2rel[16 * 4];
__constant__ __align__(16) float c_w2root[16 * 4];
__constant__ __align__(16) float c_b2[4];
__constant__ __align__(16) float c_wg1[10 * 8];
__constant__ __align__(16) float c_bg1[8];
__constant__ __align__(16) float c_wg2[8 * 8];
__constant__ __align__(16) float c_bg2[8];
__constant__ __align__(16) float c_wg3[8 * 10];
__constant__ __align__(16) float c_bg3[12];

typedef unsigned long long u64;

__device__ __forceinline__ u64 pack2(float lo, float hi) {
    u64 r; asm("mov.b64 %0, {%1, %2};" : "=l"(r) : "f"(lo), "f"(hi)); return r;
}
__device__ __forceinline__ void unpack2(float& lo, float& hi, u64 v) {
    asm("mov.b64 {%0, %1}, %2;" : "=f"(lo), "=f"(hi) : "l"(v));
}
__device__ __forceinline__ void ffma2(u64& d, u64 a, u64 b) {
    asm("fma.rn.f32x2 %0, %1, %2, %0;" : "+l"(d) : "l"(a), "l"(b));
}
__device__ __forceinline__ void cp_async16(void* dst, const void* src) {
    unsigned sa = (unsigned)__cvta_generic_to_shared(dst);
    asm volatile("cp.async.cg.shared.global [%0], [%1], 16;" :: "r"(sa), "l"(src));
}

// ---------------------------------------------------------------------------
// Kernel A: per-graph fused GraphConv x2 + global MLP. block = 64.
// f32x2 packed math in gathers and matmuls (order-preserving).
// ---------------------------------------------------------------------------
struct __align__(16) SmemA {
    float  x[NPG][XP];
    float  h1[NPG][HP];
    float2 sa[NPG * SLOT];
    int    cnt[64];
};

__global__ __launch_bounds__(64) void kernelA(
    const float* __restrict__ x, const int* __restrict__ eidx,
    const float* __restrict__ eattr, const float* __restrict__ gfeat)
{
    __shared__ SmemA s;
    const int g = blockIdx.x;
    const int tid = threadIdx.x;
    const int eb = g * EPG;
    const int base = g * NPG;

    s.cnt[tid] = 0;
    {
        const float4* xg = (const float4*)(x + (size_t)g * (NPG * 8));
        #pragma unroll
        for (int j = tid; j < 108; j += 64) {
            const int r = j >> 1, h = j & 1;
            *(float4*)&s.x[r][h * 4] = xg[j];
        }
    }
    const int   d0 = eidx[ETOT + eb + tid] - base;
    const int   s0 = eidx[eb + tid] - base;
    const float a0 = eattr[eb + tid];
    const int   d1 = eidx[ETOT + eb + tid + 64] - base;
    const int   s1 = eidx[eb + tid + 64] - base;
    const float a1 = eattr[eb + tid + 64];
    int d2 = 0, s2 = 0; float a2 = 0.f;
    if (tid < 16) {
        d2 = eidx[ETOT + eb + tid + 128] - base;
        s2 = eidx[eb + tid + 128] - base;
        a2 = eattr[eb + tid + 128];
    }
    __syncthreads();

    {
        int p = atomicAdd(&s.cnt[d0], 1);
        if (p < SLOT) s.sa[d0 * SLOT + p] = make_float2(__int_as_float(s0), a0);
        int q = atomicAdd(&s.cnt[d1], 1);
        if (q < SLOT) s.sa[d1 * SLOT + q] = make_float2(__int_as_float(s1), a1);
        if (tid < 16) {
            int r = atomicAdd(&s.cnt[d2], 1);
            if (r < SLOT) s.sa[d2 * SLOT + r] = make_float2(__int_as_float(s2), a2);
        }
    }
    __syncthreads();

    float* const arow = g_act + (size_t)g * ACTP;

    // ---- Phase 1: conv1 (lanes 0-53) / global MLP (54-63) ----------------
    if (tid < NPG) {
        u64 av2[4] = {0, 0, 0, 0};
        const int cl = min(s.cnt[tid], SLOT);
        const float2* bp = &s.sa[tid * SLOT];
        for (int p = 0; p < cl; ++p) {
            const float2 e2 = bp[p];
            const int sc = __float_as_int(e2.x);
            const ulonglong2* xp = (const ulonglong2*)&s.x[sc][0];
            const ulonglong2 x01 = xp[0];
            const ulonglong2 x23 = xp[1];
            const u64 ea = pack2(e2.y, e2.y);
            ffma2(av2[0], ea, x01.x); ffma2(av2[1], ea, x01.y);
            ffma2(av2[2], ea, x23.x); ffma2(av2[3], ea, x23.y);
        }
        float avs[8], xvs[8];
        #pragma unroll
        for (int q = 0; q < 4; ++q) unpack2(avs[q*2], avs[q*2+1], av2[q]);
        {
            const float4 r0 = *(const float4*)&s.x[tid][0];
            const float4 r1 = *(const float4*)&s.x[tid][4];
            xvs[0]=r0.x; xvs[1]=r0.y; xvs[2]=r0.z; xvs[3]=r0.w;
            xvs[4]=r1.x; xvs[5]=r1.y; xvs[6]=r1.z; xvs[7]=r1.w;
        }
        u64 acc2[8];
        {
            const u64* bp1 = (const u64*)c_b1;
            #pragma unroll
            for (int q = 0; q < 8; ++q) acc2[q] = bp1[q];
        }
        #pragma unroll
        for (int k = 0; k < 8; ++k) {
            const u64 ak = pack2(avs[k], avs[k]);
            const u64 xk = pack2(xvs[k], xvs[k]);
            const u64* wr = (const u64*)&c_w1rel[k * 16];
            const u64* wt = (const u64*)&c_w1root[k * 16];
            #pragma unroll
            for (int q = 0; q < 8; ++q) {
                ffma2(acc2[q], ak, wr[q]);
                ffma2(acc2[q], xk, wt[q]);
            }
        }
        #pragma unroll
        for (int q = 0; q < 4; ++q) {
            float l0, h0, l1, h1v;
            unpack2(l0, h0, acc2[q * 2]);
            unpack2(l1, h1v, acc2[q * 2 + 1]);
            *(float4*)&s.h1[tid][q * 4] =
                make_float4(fmaxf(l0,0.f), fmaxf(h0,0.f), fmaxf(l1,0.f), fmaxf(h1v,0.f));
        }
    } else {
        const unsigned MASK = 0xFFC00000u;
        const int l = tid - NPG;
        const float* gfp = gfeat + (size_t)g * 10;
        float v1 = 0.f;
        if (l < 8) {
            v1 = c_bg1[l];
            #pragma unroll
            for (int k = 0; k < 10; ++k) v1 = fmaf(gfp[k], c_wg1[k * 8 + l], v1);
            v1 = fmaxf(v1, 0.f);
        }
        float h1v[8];
        #pragma unroll
        for (int j = 0; j < 8; ++j) h1v[j] = __shfl_sync(MASK, v1, 22 + j);
        float v2 = 0.f;
        if (l < 8) {
            v2 = c_bg2[l];
            #pragma unroll
            for (int k = 0; k < 8; ++k) v2 = fmaf(h1v[k], c_wg2[k * 8 + l], v2);
            v2 = fmaxf(v2, 0.f);
        }
        float h2v[8];
        #pragma unroll
        for (int j = 0; j < 8; ++j) h2v[j] = __shfl_sync(MASK, v2, 22 + j);
        float v3 = c_bg3[l];
        #pragma unroll
        for (int k = 0; k < 8; ++k) v3 = fmaf(h2v[k], c_wg3[k * 10 + l], v3);
        arow[216 + l] = fmaxf(v3, 0.f);
    }
    __syncthreads();

    // ---- Phase 2: conv2 -> embeds ----------------------------------------
    if (tid < NPG) {
        u64 av2[8];
        #pragma unroll
        for (int j = 0; j < 8; ++j) av2[j] = 0;
        const int cl = min(s.cnt[tid], SLOT);
        const float2* bp = &s.sa[tid * SLOT];
        for (int p = 0; p < cl; ++p) {
            const float2 e2 = bp[p];
            const int sc = __float_as_int(e2.x);
            const ulonglong2* hp = (const ulonglong2*)&s.h1[sc][0];
            const ulonglong2 h01 = hp[0];
            const ulonglong2 h23 = hp[1];
            const ulonglong2 h45 = hp[2];
            const ulonglong2 h67 = hp[3];
            const u64 ea = pack2(e2.y, e2.y);
            ffma2(av2[0], ea, h01.x); ffma2(av2[1], ea, h01.y);
            ffma2(av2[2], ea, h23.x); ffma2(av2[3], ea, h23.y);
            ffma2(av2[4], ea, h45.x); ffma2(av2[5], ea, h45.y);
            ffma2(av2[6], ea, h67.x); ffma2(av2[7], ea, h67.y);
        }
        float avs[16], hvs[16];
        #pragma unroll
        for (int q = 0; q < 8; ++q) unpack2(avs[q*2], avs[q*2+1], av2[q]);
        #pragma unroll
        for (int q = 0; q < 4; ++q) {
            const float4 h4 = *(const float4*)&s.h1[tid][q * 4];
            hvs[q*4+0] = h4.x; hvs[q*4+1] = h4.y; hvs[q*4+2] = h4.z; hvs[q*4+3] = h4.w;
        }
        u64 c2[2] = { ((const u64*)c_b2)[0], ((const u64*)c_b2)[1] };
        #pragma unroll
        for (int k = 0; k < 16; ++k) {
            const u64 ak = pack2(avs[k], avs[k]);
            const u64 hk = pack2(hvs[k], hvs[k]);
            const u64* wr = (const u64*)&c_w2rel[k * 4];
            const u64* wt = (const u64*)&c_w2root[k * 4];
            ffma2(c2[0], ak, wr[0]); ffma2(c2[1], ak, wr[1]);
            ffma2(c2[0], hk, wt[0]); ffma2(c2[1], hk, wt[1]);
        }
        float e0, e1, e2v, e3;
        unpack2(e0, e1, c2[0]);
        unpack2(e2v, e3, c2[1]);
        *(float4*)(arow + tid * 4) =
            make_float4(fmaxf(e0,0.f), fmaxf(e1,0.f), fmaxf(e2v,0.f), fmaxf(e3,0.f));
    }
}

// ---------------------------------------------------------------------------
// Kernel B: persistent out-MLP. CTA owns a 64-col half; Ws resident in smem;
// A read DIRECTLY from g_act via LDG (L2-resident). No A smem, no tile syncs.
// grid=296 (2 CTAs/SM), block=512; thread = 2 rows x 8 cols; 128-row chunks.
// ---------------------------------------------------------------------------
#define WS3 (226 * 64)              // 14464 floats
#define SMEMB_BYTES ((WS3 + 128) * 4)   // 58368 B -> 2 CTAs/SM

__global__ __launch_bounds__(512, 2) void kernelB(
    const float* __restrict__ Wo1, const float* __restrict__ bo1,
    const float* __restrict__ Wo2)
{
    extern __shared__ float sm[];
    float* Ws  = sm;                 // [226][64]
    float* sB  = sm + WS3;           // bo1 half [64]
    float* sW2 = sB + 64;            // Wo2 half [64]

    const int tid  = threadIdx.x;
    const int half = blockIdx.x & 1;
    const int c0   = half * 64;
    const int pid  = blockIdx.x >> 1;    // 0..147

    // Ws half-columns -> smem once
    for (int j = tid; j < WS3 / 4; j += 512) {
        const int r = j >> 4, cc = (j & 15) * 4;
        cp_async16(Ws + r * 64 + cc, Wo1 + r * 128 + c0 + cc);
    }
    if (tid < 64) { sB[tid] = bo1[c0 + tid]; sW2[tid] = Wo2[c0 + tid]; }
    asm volatile("cp.async.commit_group;");
    asm volatile("cp.async.wait_group 0;");
    __syncthreads();

    const int tx = tid & 7;          // col phase
    const int ty = tid >> 3;         // 0..63: rows chunk*128 + ty, + 64
    const int cA = tx * 4;
    const int cB = 32 + tx * 4;

    const u64 bA0 = pack2(sB[cA],     sB[cA + 1]);
    const u64 bA1 = pack2(sB[cA + 2], sB[cA + 3]);
    const u64 bB0 = pack2(sB[cB],     sB[cB + 1]);
    const u64 bB1 = pack2(sB[cB + 2], sB[cB + 3]);

    for (int t = pid; t < BGRAPHS / 128; t += 148) {
        const float* A0 = g_act + (size_t)(t * 128 + ty) * ACTP;
        const float* A1 = A0 + (size_t)64 * ACTP;

        u64 acc[8];
        acc[0] = bA0; acc[1] = bA1; acc[2] = bB0; acc[3] = bB1;
        acc[4] = bA0; acc[5] = bA1; acc[6] = bB0; acc[7] = bB1;

        #pragma unroll 2
        for (int k0 = 0; k0 < 226; k0 += 2) {
            const float2 a0 = *(const float2*)(A0 + k0);
            const float2 a1 = *(const float2*)(A1 + k0);
            {
                const float* Wk = Ws + k0 * 64;
                const ulonglong2 wA = *(const ulonglong2*)(Wk + cA);
                const ulonglong2 wB = *(const ulonglong2*)(Wk + cB);
                const u64 d0 = pack2(a0.x, a0.x);
                const u64 d1 = pack2(a1.x, a1.x);
                ffma2(acc[0], d0, wA.x); ffma2(acc[1], d0, wA.y);
                ffma2(acc[2], d0, wB.x); ffma2(acc[3], d0, wB.y);
                ffma2(acc[4], d1, wA.x); ffma2(acc[5], d1, wA.y);
                ffma2(acc[6], d1, wB.x); ffma2(acc[7], d1, wB.y);
            }
            {
                const float* Wk = Ws + (k0 + 1) * 64;
                const ulonglong2 wA = *(const ulonglong2*)(Wk + cA);
                const ulonglong2 wB = *(const ulonglong2*)(Wk + cB);
                const u64 d0 = pack2(a0.y, a0.y);
                const u64 d1 = pack2(a1.y, a1.y);
                ffma2(acc[0], d0, wA.x); ffma2(acc[1], d0, wA.y);
                ffma2(acc[2], d0, wB.x); ffma2(acc[3], d0, wB.y);
                ffma2(acc[4], d1, wA.x); ffma2(acc[5], d1, wA.y);
                ffma2(acc[6], d1, wB.x); ffma2(acc[7], d1, wB.y);
            }
        }

        // Epilogue: relu * Wo2 partial dot, reduce over 8 tx lanes
        #pragma unroll
        for (int row = 0; row < 2; ++row) {
            const u64* ac = acc + row * 4;
            float p = 0.f;
            float lo, hi;
            unpack2(lo, hi, ac[0]);
            p = fmaf(fmaxf(lo, 0.f), sW2[cA],     p);
            p = fmaf(fmaxf(hi, 0.f), sW2[cA + 1], p);
            unpack2(lo, hi, ac[1]);
            p = fmaf(fmaxf(lo, 0.f), sW2[cA + 2], p);
            p = fmaf(fmaxf(hi, 0.f), sW2[cA + 3], p);
            unpack2(lo, hi, ac[2]);
            p = fmaf(fmaxf(lo, 0.f), sW2[cB],     p);
            p = fmaf(fmaxf(hi, 0.f), sW2[cB + 1], p);
            unpack2(lo, hi, ac[3]);
            p = fmaf(fmaxf(lo, 0.f), sW2[cB + 2], p);
            p = fmaf(fmaxf(hi, 0.f), sW2[cB + 3], p);
            p += __shfl_xor_sync(0xffffffffu, p, 1);
            p += __shfl_xor_sync(0xffffffffu, p, 2);
            p += __shfl_xor_sync(0xffffffffu, p, 4);
            if (tx == 0)
                g_partial[half * BGRAPHS + t * 128 + ty + row * 64] = p;
        }
    }
}

// ---------------------------------------------------------------------------
// Kernel C: combine halves + sigmoid
// ---------------------------------------------------------------------------
__global__ __launch_bounds__(512) void kernelC(const float* __restrict__ bo2,
                                               float* __restrict__ out)
{
    const int i = blockIdx.x * 512 + threadIdx.x;
    const float z = g_partial[i] + g_partial[BGRAPHS + i] + bo2[0];
    out[i] = 1.f / (1.f + expf(-z));
}

// ---------------------------------------------------------------------------
extern "C" void kernel_launch(void* const* d_in, const int* in_sizes, int n_in,
                              void* d_out, int out_size) {
    (void)in_sizes; (void)n_in; (void)out_size;
    const float* x      = (const float*)d_in[0];
    const int*   eidx   = (const int*)d_in[1];
    const float* eattr  = (const float*)d_in[2];
    const float* gfeat  = (const float*)d_in[3];
    const float* Wo1    = (const float*)d_in[16];
    const float* bo1    = (const float*)d_in[17];
    const float* Wo2    = (const float*)d_in[18];
    const float* bo2    = (const float*)d_in[19];
    float* out = (float*)d_out;

    cudaMemcpyToSymbolAsync(c_w1rel,  d_in[4],  8 * 16 * 4, 0, cudaMemcpyDeviceToDevice, 0);
    cudaMemcpyToSymbolAsync(c_b1,     d_in[5],  16 * 4,     0, cudaMemcpyDeviceToDevice, 0);
    cudaMemcpyToSymbolAsync(c_w1root, d_in[6],  8 * 16 * 4, 0, cudaMemcpyDeviceToDevice, 0);
    cudaMemcpyToSymbolAsync(c_w2rel,  d_in[7],  16 * 4 * 4, 0, cudaMemcpyDeviceToDevice, 0);
    cudaMemcpyToSymbolAsync(c_b2,     d_in[8],  4 * 4,      0, cudaMemcpyDeviceToDevice, 0);
    cudaMemcpyToSymbolAsync(c_w2root, d_in[9],  16 * 4 * 4, 0, cudaMemcpyDeviceToDevice, 0);
    cudaMemcpyToSymbolAsync(c_wg1,    d_in[10], 10 * 8 * 4, 0, cudaMemcpyDeviceToDevice, 0);
    cudaMemcpyToSymbolAsync(c_bg1,    d_in[11], 8 * 4,      0, cudaMemcpyDeviceToDevice, 0);
    cudaMemcpyToSymbolAsync(c_wg2,    d_in[12], 8 * 8 * 4,  0, cudaMemcpyDeviceToDevice, 0);
    cudaMemcpyToSymbolAsync(c_bg2,    d_in[13], 8 * 4,      0, cudaMemcpyDeviceToDevice, 0);
    cudaMemcpyToSymbolAsync(c_wg3,    d_in[14], 8 * 10 * 4, 0, cudaMemcpyDeviceToDevice, 0);
    cudaMemcpyToSymbolAsync(c_bg3,    d_in[15], 10 * 4,     0, cudaMemcpyDeviceToDevice, 0);

    cudaFuncSetAttribute(kernelB, cudaFuncAttributeMaxDynamicSharedMemorySize,
                         SMEMB_BYTES);

    kernelA<<<BGRAPHS, 64>>>(x, eidx, eattr, gfeat);
    kernelB<<<296, 512, SMEMB_BYTES>>>(Wo1, bo1, Wo2);
    kernelC<<<BGRAPHS / 512, 512>>>(bo2, out);
}

// round 17
// speedup vs baseline: 1.0864x; 1.0864x over previous
#include <cuda_runtime.h>
#include <math.h>

#define BGRAPHS 32768
#define NPG 54
#define EPG 144
#define ETOT (BGRAPHS * EPG)
#define ACTP 228            // padded act row (226 used)
#define SLOT 17             // slots per node; odd stride -> conflict-free sa
#define XP 12               // x row pad (floats)
#define HP 20               // h1 row pad (floats)

// Staging: concat([embeds, g]) rows [B, 228]; partial out sums [2][B]
__device__ __align__(16) float g_act[(size_t)BGRAPHS * ACTP];
__device__ __align__(16) float g_partial[2 * BGRAPHS];

// ---------------- constant weights (graph-captured D2D copies) -------------
__constant__ __align__(16) float c_w1rel[8 * 16];
__constant__ __align__(16) float c_w1root[8 * 16];
__constant__ __align__(16) float c_b1[16];
__constant__ __align__(16) float c_w2rel[16 * 4];
__constant__ __align__(16) float c_w2root[16 * 4];
__constant__ __align__(16) float c_b2[4];
__constant__ __align__(16) float c_wg1[10 * 8];
__constant__ __align__(16) float c_bg1[8];
__constant__ __align__(16) float c_wg2[8 * 8];
__constant__ __align__(16) float c_bg2[8];
__constant__ __align__(16) float c_wg3[8 * 10];
__constant__ __align__(16) float c_bg3[12];

typedef unsigned long long u64;

__device__ __forceinline__ u64 pack2(float lo, float hi) {
    u64 r; asm("mov.b64 %0, {%1, %2};" : "=l"(r) : "f"(lo), "f"(hi)); return r;
}
__device__ __forceinline__ void unpack2(float& lo, float& hi, u64 v) {
    asm("mov.b64 {%0, %1}, %2;" : "=f"(lo), "=f"(hi) : "l"(v));
}
__device__ __forceinline__ void ffma2(u64& d, u64 a, u64 b) {
    asm("fma.rn.f32x2 %0, %1, %2, %0;" : "+l"(d) : "l"(a), "l"(b));
}
__device__ __forceinline__ void cp_async16(void* dst, const void* src) {
    unsigned sa = (unsigned)__cvta_generic_to_shared(dst);
    asm volatile("cp.async.cg.shared.global [%0], [%1], 16;" :: "r"(sa), "l"(src));
}

// ---------------------------------------------------------------------------
// Kernel A: per-graph fused GraphConv x2 + global MLP. block = 64, occ 20.
// Edge record = ONE u32: att with low-6 mantissa bits replaced by src index
// (rel perturbation of att <= 7.5e-6, far under the 1e-3 tolerance).
// ---------------------------------------------------------------------------
struct __align__(16) SmemA {
    float    x[NPG][XP];         // 2592 B
    float    h1[NPG][HP];        // 4320 B
    unsigned sa[NPG * SLOT];     // 3672 B (stride 17 words: 32-bank spread)
    int      cnt[64];            // 256 B
};

__global__ __launch_bounds__(64, 20) void kernelA(
    const float* __restrict__ x, const int* __restrict__ eidx,
    const float* __restrict__ eattr, const float* __restrict__ gfeat)
{
    __shared__ SmemA s;
    const int g = blockIdx.x;
    const int tid = threadIdx.x;
    const int eb = g * EPG;
    const int base = g * NPG;

    s.cnt[tid] = 0;
    {
        const float4* xg = (const float4*)(x + (size_t)g * (NPG * 8));
        #pragma unroll
        for (int j = tid; j < 108; j += 64) {
            const int r = j >> 1, h = j & 1;
            *(float4*)&s.x[r][h * 4] = xg[j];
        }
    }
    const int      d0 = eidx[ETOT + eb + tid] - base;
    const unsigned p0 = (__float_as_uint(eattr[eb + tid]) & ~63u)
                      | (unsigned)(eidx[eb + tid] - base);
    const int      d1 = eidx[ETOT + eb + tid + 64] - base;
    const unsigned p1 = (__float_as_uint(eattr[eb + tid + 64]) & ~63u)
                      | (unsigned)(eidx[eb + tid + 64] - base);
    int d2 = 0; unsigned p2 = 0;
    if (tid < 16) {
        d2 = eidx[ETOT + eb + tid + 128] - base;
        p2 = (__float_as_uint(eattr[eb + tid + 128]) & ~63u)
           | (unsigned)(eidx[eb + tid + 128] - base);
    }
    __syncthreads();

    {
        int p = atomicAdd(&s.cnt[d0], 1);
        if (p < SLOT) s.sa[d0 * SLOT + p] = p0;
        int q = atomicAdd(&s.cnt[d1], 1);
        if (q < SLOT) s.sa[d1 * SLOT + q] = p1;
        if (tid < 16) {
            int r = atomicAdd(&s.cnt[d2], 1);
            if (r < SLOT) s.sa[d2 * SLOT + r] = p2;
        }
    }
    __syncthreads();

    float* const arow = g_act + (size_t)g * ACTP;

    // ---- Phase 1: conv1 (lanes 0-53) / global MLP (54-63) ----------------
    if (tid < NPG) {
        u64 av2[4] = {0, 0, 0, 0};
        const int cl = min(s.cnt[tid], SLOT);
        const unsigned* bp = &s.sa[tid * SLOT];
        for (int p = 0; p < cl; ++p) {
            const unsigned u = bp[p];
            const int sc = (int)(u & 63u);
            const float at = __uint_as_float(u & ~63u);
            const ulonglong2* xp = (const ulonglong2*)&s.x[sc][0];
            const ulonglong2 x01 = xp[0];
            const ulonglong2 x23 = xp[1];
            const u64 ea = pack2(at, at);
            ffma2(av2[0], ea, x01.x); ffma2(av2[1], ea, x01.y);
            ffma2(av2[2], ea, x23.x); ffma2(av2[3], ea, x23.y);
        }
        u64 acc2[8];
        {
            const u64* bp1 = (const u64*)c_b1;
            #pragma unroll
            for (int q = 0; q < 8; ++q) acc2[q] = bp1[q];
        }
        const ulonglong2* xr = (const ulonglong2*)&s.x[tid][0];
        const ulonglong2 xr01 = xr[0];
        const ulonglong2 xr23 = xr[1];
        const u64 xroot[4] = { xr01.x, xr01.y, xr23.x, xr23.y };
        #pragma unroll
        for (int kq = 0; kq < 4; ++kq) {
            float alo, ahi, xlo, xhi;
            unpack2(alo, ahi, av2[kq]);
            unpack2(xlo, xhi, xroot[kq]);
            {   // k = 2*kq
                const u64 ak = pack2(alo, alo);
                const u64 xk = pack2(xlo, xlo);
                const u64* wr = (const u64*)&c_w1rel[(2 * kq) * 16];
                const u64* wt = (const u64*)&c_w1root[(2 * kq) * 16];
                #pragma unroll
                for (int q = 0; q < 8; ++q) {
                    ffma2(acc2[q], ak, wr[q]);
                    ffma2(acc2[q], xk, wt[q]);
                }
            }
            {   // k = 2*kq+1
                const u64 ak = pack2(ahi, ahi);
                const u64 xk = pack2(xhi, xhi);
                const u64* wr = (const u64*)&c_w1rel[(2 * kq + 1) * 16];
                const u64* wt = (const u64*)&c_w1root[(2 * kq + 1) * 16];
                #pragma unroll
                for (int q = 0; q < 8; ++q) {
                    ffma2(acc2[q], ak, wr[q]);
                    ffma2(acc2[q], xk, wt[q]);
                }
            }
        }
        #pragma unroll
        for (int q = 0; q < 4; ++q) {
            float l0, h0, l1, h1v;
            unpack2(l0, h0, acc2[q * 2]);
            unpack2(l1, h1v, acc2[q * 2 + 1]);
            *(float4*)&s.h1[tid][q * 4] =
                make_float4(fmaxf(l0,0.f), fmaxf(h0,0.f), fmaxf(l1,0.f), fmaxf(h1v,0.f));
        }
    } else {
        const unsigned MASK = 0xFFC00000u;
        const int l = tid - NPG;
        const float* gfp = gfeat + (size_t)g * 10;
        float v1 = 0.f;
        if (l < 8) {
            v1 = c_bg1[l];
            #pragma unroll
            for (int k = 0; k < 10; ++k) v1 = fmaf(gfp[k], c_wg1[k * 8 + l], v1);
            v1 = fmaxf(v1, 0.f);
        }
        float h1v[8];
        #pragma unroll
        for (int j = 0; j < 8; ++j) h1v[j] = __shfl_sync(MASK, v1, 22 + j);
        float v2 = 0.f;
        if (l < 8) {
            v2 = c_bg2[l];
            #pragma unroll
            for (int k = 0; k < 8; ++k) v2 = fmaf(h1v[k], c_wg2[k * 8 + l], v2);
            v2 = fmaxf(v2, 0.f);
        }
        float h2v[8];
        #pragma unroll
        for (int j = 0; j < 8; ++j) h2v[j] = __shfl_sync(MASK, v2, 22 + j);
        float v3 = c_bg3[l];
        #pragma unroll
        for (int k = 0; k < 8; ++k) v3 = fmaf(h2v[k], c_wg3[k * 10 + l], v3);
        arow[216 + l] = fmaxf(v3, 0.f);
    }
    __syncthreads();

    // ---- Phase 2: conv2 -> embeds ----------------------------------------
    if (tid < NPG) {
        u64 av2[8];
        #pragma unroll
        for (int j = 0; j < 8; ++j) av2[j] = 0;
        const int cl = min(s.cnt[tid], SLOT);
        const unsigned* bp = &s.sa[tid * SLOT];
        for (int p = 0; p < cl; ++p) {
            const unsigned u = bp[p];
            const int sc = (int)(u & 63u);
            const float at = __uint_as_float(u & ~63u);
            const ulonglong2* hp = (const ulonglong2*)&s.h1[sc][0];
            const ulonglong2 h01 = hp[0];
            const ulonglong2 h23 = hp[1];
            const ulonglong2 h45 = hp[2];
            const ulonglong2 h67 = hp[3];
            const u64 ea = pack2(at, at);
            ffma2(av2[0], ea, h01.x); ffma2(av2[1], ea, h01.y);
            ffma2(av2[2], ea, h23.x); ffma2(av2[3], ea, h23.y);
            ffma2(av2[4], ea, h45.x); ffma2(av2[5], ea, h45.y);
            ffma2(av2[6], ea, h67.x); ffma2(av2[7], ea, h67.y);
        }
        u64 c2[2] = { ((const u64*)c_b2)[0], ((const u64*)c_b2)[1] };
        const u64* hself = (const u64*)&s.h1[tid][0];
        #pragma unroll
        for (int kq = 0; kq < 8; ++kq) {
            float alo, ahi, hlo, hhi;
            unpack2(alo, ahi, av2[kq]);
            unpack2(hlo, hhi, hself[kq]);
            {   // k = 2*kq
                const u64 ak = pack2(alo, alo);
                const u64 hk = pack2(hlo, hlo);
                const u64* wr = (const u64*)&c_w2rel[(2 * kq) * 4];
                const u64* wt = (const u64*)&c_w2root[(2 * kq) * 4];
                ffma2(c2[0], ak, wr[0]); ffma2(c2[1], ak, wr[1]);
                ffma2(c2[0], hk, wt[0]); ffma2(c2[1], hk, wt[1]);
            }
            {   // k = 2*kq+1
                const u64 ak = pack2(ahi, ahi);
                const u64 hk = pack2(hhi, hhi);
                const u64* wr = (const u64*)&c_w2rel[(2 * kq + 1) * 4];
                const u64* wt = (const u64*)&c_w2root[(2 * kq + 1) * 4];
                ffma2(c2[0], ak, wr[0]); ffma2(c2[1], ak, wr[1]);
                ffma2(c2[0], hk, wt[0]); ffma2(c2[1], hk, wt[1]);
            }
        }
        float e0, e1, e2v, e3;
        unpack2(e0, e1, c2[0]);
        unpack2(e2v, e3, c2[1]);
        *(float4*)(arow + tid * 4) =
            make_float4(fmaxf(e0,0.f), fmaxf(e1,0.f), fmaxf(e2v,0.f), fmaxf(e3,0.f));
    }
}

// ---------------------------------------------------------------------------
// Kernel B: persistent out-MLP (R15 design). CTA owns a 64-col half
// (Ws resident once); 128-row smem tiles; thread = 2 rows x 8 cols.
// grid=148, block=512.
// ---------------------------------------------------------------------------
#define BROWS 128
#define NT3 (BGRAPHS / BROWS)       // 256 row tiles
#define WS3 (226 * 64)              // 14464 floats
#define AS3 (BROWS * ACTP)          // 29184 floats
#define SMEMB_BYTES ((WS3 + AS3 + 128) * 4)   // 175104 B

__global__ __launch_bounds__(512, 1) void kernelB(
    const float* __restrict__ Wo1, const float* __restrict__ bo1,
    const float* __restrict__ Wo2)
{
    extern __shared__ float sm[];
    float* Ws  = sm;                 // [226][64]
    float* As  = sm + WS3;           // [128][228]
    float* sB  = sm + WS3 + AS3;     // bo1 half [64]
    float* sW2 = sB + 64;            // Wo2 half [64]

    const int tid  = threadIdx.x;
    const int half = blockIdx.x & 1;
    const int c0   = half * 64;
    const int pid  = blockIdx.x >> 1;    // 0..73

    for (int j = tid; j < WS3 / 4; j += 512) {
        const int r = j >> 4, cc = (j & 15) * 4;
        cp_async16(Ws + r * 64 + cc, Wo1 + r * 128 + c0 + cc);
    }
    if (tid < 64) { sB[tid] = bo1[c0 + tid]; sW2[tid] = Wo2[c0 + tid]; }

    const int tx = tid & 7;
    const int ty = tid >> 3;             // 0..63: rows ty, ty+64
    const int cA = tx * 4;
    const int cB = 32 + tx * 4;

    for (int t = pid; t < NT3; t += 74) {
        {
            const float4* src = (const float4*)(g_act + (size_t)t * (BROWS * ACTP));
            float4* dst = (float4*)As;
            for (int j = tid; j < AS3 / 4; j += 512) cp_async16(dst + j, src + j);
            asm volatile("cp.async.commit_group;");
            asm volatile("cp.async.wait_group 0;");
        }
        __syncthreads();

        u64 acc[8];
        {
            const u64 bA0 = pack2(sB[cA],     sB[cA + 1]);
            const u64 bA1 = pack2(sB[cA + 2], sB[cA + 3]);
            const u64 bB0 = pack2(sB[cB],     sB[cB + 1]);
            const u64 bB1 = pack2(sB[cB + 2], sB[cB + 3]);
            acc[0] = bA0; acc[1] = bA1; acc[2] = bB0; acc[3] = bB1;
            acc[4] = bA0; acc[5] = bA1; acc[6] = bB0; acc[7] = bB1;
        }

        const float* A0 = As + ty * ACTP;
        const float* A1 = As + (ty + 64) * ACTP;

        #pragma unroll 2
        for (int k0 = 0; k0 < 226; k0 += 2) {
            const float2 a0 = *(const float2*)(A0 + k0);
            const float2 a1 = *(const float2*)(A1 + k0);
            {
                const float* Wk = Ws + k0 * 64;
                const ulonglong2 wA = *(const ulonglong2*)(Wk + cA);
                const ulonglong2 wB = *(const ulonglong2*)(Wk + cB);
                const u64 d0 = pack2(a0.x, a0.x);
                const u64 d1 = pack2(a1.x, a1.x);
                ffma2(acc[0], d0, wA.x); ffma2(acc[1], d0, wA.y);
                ffma2(acc[2], d0, wB.x); ffma2(acc[3], d0, wB.y);
                ffma2(acc[4], d1, wA.x); ffma2(acc[5], d1, wA.y);
                ffma2(acc[6], d1, wB.x); ffma2(acc[7], d1, wB.y);
            }
            {
                const float* Wk = Ws + (k0 + 1) * 64;
                const ulonglong2 wA = *(const ulonglong2*)(Wk + cA);
                const ulonglong2 wB = *(const ulonglong2*)(Wk + cB);
                const u64 d0 = pack2(a0.y, a0.y);
                const u64 d1 = pack2(a1.y, a1.y);
                ffma2(acc[0], d0, wA.x); ffma2(acc[1], d0, wA.y);
                ffma2(acc[2], d0, wB.x); ffma2(acc[3], d0, wB.y);
                ffma2(acc[4], d1, wA.x); ffma2(acc[5], d1, wA.y);
                ffma2(acc[6], d1, wB.x); ffma2(acc[7], d1, wB.y);
            }
        }

        #pragma unroll
        for (int row = 0; row < 2; ++row) {
            const u64* ac = acc + row * 4;
            float p = 0.f;
            float lo, hi;
            unpack2(lo, hi, ac[0]);
            p = fmaf(fmaxf(lo, 0.f), sW2[cA],     p);
            p = fmaf(fmaxf(hi, 0.f), sW2[cA + 1], p);
            unpack2(lo, hi, ac[1]);
            p = fmaf(fmaxf(lo, 0.f), sW2[cA + 2], p);
            p = fmaf(fmaxf(hi, 0.f), sW2[cA + 3], p);
            unpack2(lo, hi, ac[2]);
            p = fmaf(fmaxf(lo, 0.f), sW2[cB],     p);
            p = fmaf(fmaxf(hi, 0.f), sW2[cB + 1], p);
            unpack2(lo, hi, ac[3]);
            p = fmaf(fmaxf(lo, 0.f), sW2[cB + 2], p);
            p = fmaf(fmaxf(hi, 0.f), sW2[cB + 3], p);
            p += __shfl_xor_sync(0xffffffffu, p, 1);
            p += __shfl_xor_sync(0xffffffffu, p, 2);
            p += __shfl_xor_sync(0xffffffffu, p, 4);
            if (tx == 0)
                g_partial[half * BGRAPHS + t * BROWS + ty + row * 64] = p;
        }
        __syncthreads();
    }
}

// ---------------------------------------------------------------------------
// Kernel C: combine halves + sigmoid
// ---------------------------------------------------------------------------
__global__ __launch_bounds__(512) void kernelC(const float* __restrict__ bo2,
                                               float* __restrict__ out)
{
    const int i = blockIdx.x * 512 + threadIdx.x;
    const float z = g_partial[i] + g_partial[BGRAPHS + i] + bo2[0];
    out[i] = 1.f / (1.f + expf(-z));
}

// ---------------------------------------------------------------------------
extern "C" void kernel_launch(void* const* d_in, const int* in_sizes, int n_in,
                              void* d_out, int out_size) {
    (void)in_sizes; (void)n_in; (void)out_size;
    const float* x      = (const float*)d_in[0];
    const int*   eidx   = (const int*)d_in[1];
    const float* eattr  = (const float*)d_in[2];
    const float* gfeat  = (const float*)d_in[3];
    const float* Wo1    = (const float*)d_in[16];
    const float* bo1    = (const float*)d_in[17];
    const float* Wo2    = (const float*)d_in[18];
    const float* bo2    = (const float*)d_in[19];
    float* out = (float*)d_out;

    cudaMemcpyToSymbolAsync(c_w1rel,  d_in[4],  8 * 16 * 4, 0, cudaMemcpyDeviceToDevice, 0);
    cudaMemcpyToSymbolAsync(c_b1,     d_in[5],  16 * 4,     0, cudaMemcpyDeviceToDevice, 0);
    cudaMemcpyToSymbolAsync(c_w1root, d_in[6],  8 * 16 * 4, 0, cudaMemcpyDeviceToDevice, 0);
    cudaMemcpyToSymbolAsync(c_w2rel,  d_in[7],  16 * 4 * 4, 0, cudaMemcpyDeviceToDevice, 0);
    cudaMemcpyToSymbolAsync(c_b2,     d_in[8],  4 * 4,      0, cudaMemcpyDeviceToDevice, 0);
    cudaMemcpyToSymbolAsync(c_w2root, d_in[9],  16 * 4 * 4, 0, cudaMemcpyDeviceToDevice, 0);
    cudaMemcpyToSymbolAsync(c_wg1,    d_in[10], 10 * 8 * 4, 0, cudaMemcpyDeviceToDevice, 0);
    cudaMemcpyToSymbolAsync(c_bg1,    d_in[11], 8 * 4,      0, cudaMemcpyDeviceToDevice, 0);
    cudaMemcpyToSymbolAsync(c_wg2,    d_in[12], 8 * 8 * 4,  0, cudaMemcpyDeviceToDevice, 0);
    cudaMemcpyToSymbolAsync(c_bg2,    d_in[13], 8 * 4,      0, cudaMemcpyDeviceToDevice, 0);
    cudaMemcpyToSymbolAsync(c_wg3,    d_in[14], 8 * 10 * 4, 0, cudaMemcpyDeviceToDevice, 0);
    cudaMemcpyToSymbolAsync(c_bg3,    d_in[15], 10 * 4,     0, cudaMemcpyDeviceToDevice, 0);

    cudaFuncSetAttribute(kernelB, cudaFuncAttributeMaxDynamicSharedMemorySize,
                         SMEMB_BYTES);

    kernelA<<<BGRAPHS, 64>>>(x, eidx, eattr, gfeat);
    kernelB<<<148, 512, SMEMB_BYTES>>>(Wo1, bo1, Wo2);
    kernelC<<<BGRAPHS / 512, 512>>>(bo2, out);
}